// round 16
// baseline (speedup 1.0000x reference)
#include <cuda_runtime.h>
#include <cuda_bf16.h>
#include <math.h>
#include <stdint.h>

#define H    768
#define FFD  3072
#define BB   4
#define SS   1024
#define NHH  12
#define HDD  64
#define NTOK 4096
#define NLAYER 6
#define H3   2304   // 3*H packed QKV

typedef __nv_bfloat16 bf16;

// ---------------- device scratch ----------------
__device__ float g_t [NTOK*H];
__device__ float g_at[NTOK*H];
__device__ float g_x [NTOK*H];
__device__ float g_bqkv[H3];
__device__ bf16 g_xh[NTOK*H],   g_xl[NTOK*H];
__device__ bf16 g_qkvh[NTOK*H3], g_qkvl[NTOK*H3];
__device__ bf16 g_ch[NTOK*H],   g_cl[NTOK*H];
__device__ bf16 g_ah[NTOK*H],   g_al[NTOK*H];
__device__ bf16 g_fh[NTOK*FFD], g_fl[NTOK*FFD];
__device__ bf16 g_wqkvh[H3*H],  g_wqkvl[H3*H];
__device__ bf16 g_wah[H*H],     g_wal[H*H];
__device__ bf16 g_w1h[H*FFD],   g_w1l[H*FFD];
__device__ bf16 g_w2h[H*FFD],   g_w2l[H*FFD];

#define EPI_NONE      0
#define EPI_BIAS      1
#define EPI_GELU      2
#define EPI_BIASRES   3
#define OUT_F32   0
#define OUT_SPLIT 1

__device__ __forceinline__ uint32_t su32(const void* p) {
    return (uint32_t)__cvta_generic_to_shared(p);
}
__device__ __forceinline__ void cpa16(void* s, const void* g) {
    asm volatile("cp.async.cg.shared.global [%0], [%1], 16;" :: "r"(su32(s)), "l"(g));
}
__device__ __forceinline__ void cp_commit() { asm volatile("cp.async.commit_group;"); }
template<int N> __device__ __forceinline__ void cp_wait() {
    asm volatile("cp.async.wait_group %0;" :: "n"(N));
}
__device__ __forceinline__ void mma16(float c[4], const uint32_t a[4], const uint32_t b[2]) {
    asm volatile(
        "mma.sync.aligned.m16n8k16.row.col.f32.bf16.bf16.f32 "
        "{%0,%1,%2,%3}, {%4,%5,%6,%7}, {%8,%9}, {%0,%1,%2,%3};\n"
        : "+f"(c[0]), "+f"(c[1]), "+f"(c[2]), "+f"(c[3])
        : "r"(a[0]), "r"(a[1]), "r"(a[2]), "r"(a[3]), "r"(b[0]), "r"(b[1]));
}
__device__ __forceinline__ void ldsm4(uint32_t r[4], uint32_t addr) {
    asm volatile("ldmatrix.sync.aligned.m8n8.x4.shared.b16 {%0,%1,%2,%3}, [%4];"
                 : "=r"(r[0]), "=r"(r[1]), "=r"(r[2]), "=r"(r[3]) : "r"(addr));
}
__device__ __forceinline__ void ldsm4t(uint32_t r[4], uint32_t addr) {
    asm volatile("ldmatrix.sync.aligned.m8n8.x4.trans.shared.b16 {%0,%1,%2,%3}, [%4];"
                 : "=r"(r[0]), "=r"(r[1]), "=r"(r[2]), "=r"(r[3]) : "r"(addr));
}
__device__ __forceinline__ void spbf(float x, bf16& hi, bf16& lo) {
    hi = __float2bfloat16(x);
    lo = __float2bfloat16(x - __bfloat162float(hi));
}
__device__ __forceinline__ void pack2(float x, float y, uint32_t& hi, uint32_t& lo) {
    bf16 hx = __float2bfloat16(x), hy = __float2bfloat16(y);
    bf16 lx = __float2bfloat16(x - __bfloat162float(hx));
    bf16 ly = __float2bfloat16(y - __bfloat162float(hy));
    hi = ((uint32_t)__bfloat16_as_ushort(hy) << 16) | __bfloat16_as_ushort(hx);
    lo = ((uint32_t)__bfloat16_as_ushort(ly) << 16) | __bfloat16_as_ushort(lx);
}

// ---------------------------------------------------------------------------
// bf16 split GEMM: C = (Ah+Al)(Bh+Bl)^T, 3 terms, fp32 accum.
// CTA tile 128x128, BK=32, 8 warps (4m x 2n), warp tile 32x64.
// 3-stage cp.async ring, one __syncthreads per chunk, 2 CTAs/SM.
// Per chunk/warp: 96 HMMA vs 24 LDSM (4:1 issue ratio).
// ---------------------------------------------------------------------------
template<int EPI, int OUTM>
__global__ void __launch_bounds__(256, 2)
gemm_bf(const bf16* __restrict__ Ah, const bf16* __restrict__ Al,
        const bf16* __restrict__ Bh, const bf16* __restrict__ Bl,
        const float* __restrict__ bias, const float* __restrict__ res,
        float* __restrict__ Cf, bf16* __restrict__ Ch, bf16* __restrict__ Cl,
        int K, int lda, int ldb, int ldc)
{
    extern __shared__ __align__(16) char smem[];   // 3 stages x 32768 B
    const int tid = threadIdx.x, lane = tid & 31, warp = tid >> 5;
    const int row0 = blockIdx.y * 128, col0 = blockIdx.x * 128;
    const int wm = warp & 3, wn = warp >> 2;
    const int q = lane >> 2, t = lane & 3;
    const int la = lane & 15, ca = lane >> 4;
    const int mb = lane >> 3;
    const int rb = ((mb >> 1) << 3) + (lane & 7), cb = mb & 1;
    const uint32_t sbase = su32(smem);

    auto load_stage = [&](int s, int k0) {
        char* base = smem + s * 32768;
        #pragma unroll
        for (int i = 0; i < 4; i++) {              // A hi+lo: 1024 chunks
            int c = tid + i * 256, tile = c >> 9, rem = c & 511;
            int r = rem >> 2, cj = rem & 3;
            const bf16* src = (tile ? Al : Ah) + (long)(row0 + r) * lda + k0 + cj * 8;
            cpa16(base + tile * 8192 + r * 64 + ((cj ^ ((r >> 1) & 3)) * 16), src);
        }
        #pragma unroll
        for (int i = 0; i < 4; i++) {              // B hi+lo: 1024 chunks
            int c = tid + i * 256, tile = c >> 9, rem = c & 511;
            int r = rem >> 2, cj = rem & 3;
            const bf16* src = (tile ? Bl : Bh) + (long)(col0 + r) * ldb + k0 + cj * 8;
            cpa16(base + 16384 + tile * 8192 + r * 64 + ((cj ^ ((r >> 1) & 3)) * 16), src);
        }
        cp_commit();
    };

    float acc[2][8][4] = {};

    auto compute = [&](int s) {
        const uint32_t ab = sbase + s * 32768;
        #pragma unroll
        for (int ks = 0; ks < 2; ks++) {
            uint32_t ahi[2][4], alo[2][4];
            #pragma unroll
            for (int mt = 0; mt < 2; mt++) {
                const int r = wm * 32 + mt * 16 + la;
                const int c = 2 * ks + ca;
                const uint32_t ad = ab + r * 64 + ((c ^ ((r >> 1) & 3)) * 16);
                ldsm4(ahi[mt], ad);
                ldsm4(alo[mt], ad + 8192);
            }
            #pragma unroll
            for (int p = 0; p < 4; p++) {          // B pair loaded, used, retired
                const int r = wn * 64 + p * 16 + rb;
                const int c = 2 * ks + cb;
                const uint32_t bd = ab + 16384 + r * 64 + ((c ^ ((r >> 1) & 3)) * 16);
                uint32_t th[4], tl[4];
                ldsm4(th, bd);
                ldsm4(tl, bd + 8192);
                uint32_t b0h[2] = {th[0], th[1]}, b1h[2] = {th[2], th[3]};
                uint32_t b0l[2] = {tl[0], tl[1]}, b1l[2] = {tl[2], tl[3]};
                #pragma unroll
                for (int mt = 0; mt < 2; mt++) {
                    mma16(acc[mt][2*p],   ahi[mt], b0h);
                    mma16(acc[mt][2*p],   ahi[mt], b0l);
                    mma16(acc[mt][2*p],   alo[mt], b0h);
                    mma16(acc[mt][2*p+1], ahi[mt], b1h);
                    mma16(acc[mt][2*p+1], ahi[mt], b1l);
                    mma16(acc[mt][2*p+1], alo[mt], b1h);
                }
            }
        }
    };

    const int nIt = K >> 5;
    load_stage(0, 0);
    load_stage(1, 32);
    for (int it = 0; it < nIt; it++) {
        if (it + 1 < nIt) cp_wait<1>();
        else              cp_wait<0>();
        __syncthreads();   // stage it%3 ready; stage it-1 fully consumed
        if (it + 2 < nIt) load_stage((it + 2) % 3, (it + 2) << 5);
        compute(it % 3);
    }

    #pragma unroll
    for (int mt = 0; mt < 2; mt++)
        #pragma unroll
        for (int nt = 0; nt < 8; nt++) {
            const int cg = col0 + wn * 64 + nt * 8 + 2 * t;
            #pragma unroll
            for (int h2 = 0; h2 < 2; h2++) {
                const int rg = row0 + wm * 32 + mt * 16 + q + h2 * 8;
                float v0 = acc[mt][nt][h2 * 2 + 0];
                float v1 = acc[mt][nt][h2 * 2 + 1];
                if (EPI != EPI_NONE) {
                    v0 += bias[cg];
                    v1 += bias[cg + 1];
                    if (EPI == EPI_GELU) {
                        v0 = 0.5f * v0 * (1.0f + erff(v0 * 0.70710678118654752440f));
                        v1 = 0.5f * v1 * (1.0f + erff(v1 * 0.70710678118654752440f));
                    } else if (EPI == EPI_BIASRES) {
                        v0 += res[(long)rg * ldc + cg];
                        v1 += res[(long)rg * ldc + cg + 1];
                    }
                }
                const long o = (long)rg * ldc + cg;
                if (OUTM == OUT_F32) {
                    *(float2*)(Cf + o) = make_float2(v0, v1);
                } else {
                    bf16 h0, l0, h1, l1;
                    spbf(v0, h0, l0); spbf(v1, h1, l1);
                    *(__nv_bfloat162*)(Ch + o) = __halves2bfloat162(h0, h1);
                    *(__nv_bfloat162*)(Cl + o) = __halves2bfloat162(l0, l1);
                }
            }
        }
}

// ---------------------------------------------------------------------------
// Fused flash attention (unchanged, known-good).
// ---------------------------------------------------------------------------
__global__ void __launch_bounds__(256, 1)
fattn(const bf16* __restrict__ QKVh, const bf16* __restrict__ QKVl,
      const float* __restrict__ mask,
      bf16* __restrict__ Ch, bf16* __restrict__ Cl)
{
    extern __shared__ __align__(16) char smem[];
    const int tid = threadIdx.x, lane = tid & 31, warp = tid >> 5;
    const int bh = blockIdx.y, bb = bh / NHH, hh = bh % NHH;
    const int row0 = blockIdx.x * 128;
    const long ibase = (long)bb * SS * H3 + hh * HDD;
    const long obase = (long)bb * SS * H  + hh * HDD;
    const int q = lane >> 2, t = lane & 3;
    const int la = lane & 15, ca = lane >> 4;
    const int mb = lane >> 3;
    const int rb = ((mb >> 1) << 3) + (lane & 7), cb = mb & 1;
    const uint32_t sbase = su32(smem);
    float* mask_s = (float*)(smem + 163840);

    for (int i = tid; i < SS; i += 256) mask_s[i] = mask[(long)bb * SS + i];

    auto load_q = [&]() {
        #pragma unroll
        for (int i = 0; i < 8; i++) {
            int c = tid + i * 256, buf = c >> 10, rem = c & 1023;
            int r = rem >> 3, cj = rem & 7;
            const bf16* src = (buf ? QKVl : QKVh) + ibase + (long)(row0 + r) * H3 + cj * 8;
            cpa16(smem + buf * 16384 + r * 128 + ((cj ^ (r & 7)) * 16), src);
        }
    };
    auto load_kv = [&](int s, int blk) {
        char* sb = smem + 32768 + s * 65536;
        #pragma unroll
        for (int i = 0; i < 16; i++) {
            int c = tid + i * 256, buf = c >> 10, rem = c & 1023;
            int r = rem >> 3, cj = rem & 7;
            const bf16* arr = (buf & 1) ? QKVl : QKVh;
            const int coff = (buf >> 1) ? 2 * H : H;
            const bf16* src = arr + ibase + coff + (long)(blk * 128 + r) * H3 + cj * 8;
            cpa16(sb + buf * 16384 + r * 128 + ((cj ^ (r & 7)) * 16), src);
        }
    };

    load_q();
    load_kv(0, 0);
    cp_commit();
    load_kv(1, 1);
    cp_commit();
    cp_wait<1>();
    __syncthreads();

    uint32_t qfh[4][4], qfl[4][4];
    #pragma unroll
    for (int kk = 0; kk < 4; kk++) {
        const int r = warp * 16 + la;
        const int c = 2 * kk + ca;
        const uint32_t ad = sbase + r * 128 + ((c ^ (r & 7)) * 16);
        ldsm4(qfh[kk], ad);
        ldsm4(qfl[kk], ad + 16384);
    }

    float m0 = -INFINITY, m1 = -INFINITY, l0 = 0.f, l1 = 0.f;
    float o[8][4] = {};

    for (int j = 0; j < 8; j++) {
        const uint32_t stb = sbase + 32768 + (j & 1) * 65536;

        float s[16][4];
        #pragma unroll
        for (int i = 0; i < 16; i++)
            #pragma unroll
            for (int c = 0; c < 4; c++) s[i][c] = 0.f;
        #pragma unroll
        for (int p = 0; p < 8; p++) {
            #pragma unroll
            for (int kk = 0; kk < 4; kk++) {
                const int r = p * 16 + rb;
                const int c = 2 * kk + cb;
                const uint32_t bd = stb + r * 128 + ((c ^ (r & 7)) * 16);
                uint32_t th[4], tl[4];
                ldsm4(th, bd);
                ldsm4(tl, bd + 16384);
                uint32_t b0h[2] = {th[0], th[1]}, b1h[2] = {th[2], th[3]};
                uint32_t b0l[2] = {tl[0], tl[1]}, b1l[2] = {tl[2], tl[3]};
                mma16(s[2*p],   qfh[kk], b0h);
                mma16(s[2*p],   qfh[kk], b0l);
                mma16(s[2*p],   qfl[kk], b0h);
                mma16(s[2*p+1], qfh[kk], b1h);
                mma16(s[2*p+1], qfh[kk], b1l);
                mma16(s[2*p+1], qfl[kk], b1h);
            }
        }

        #pragma unroll
        for (int nt = 0; nt < 16; nt++) {
            const int cc = j * 128 + nt * 8 + 2 * t;
            const float mk0 = mask_s[cc], mk1 = mask_s[cc + 1];
            s[nt][0] = s[nt][0] * 0.125f + mk0;
            s[nt][1] = s[nt][1] * 0.125f + mk1;
            s[nt][2] = s[nt][2] * 0.125f + mk0;
            s[nt][3] = s[nt][3] * 0.125f + mk1;
        }

        float p0 = -INFINITY, p1 = -INFINITY;
        #pragma unroll
        for (int nt = 0; nt < 16; nt++) {
            p0 = fmaxf(p0, fmaxf(s[nt][0], s[nt][1]));
            p1 = fmaxf(p1, fmaxf(s[nt][2], s[nt][3]));
        }
        p0 = fmaxf(p0, __shfl_xor_sync(~0u, p0, 1));
        p0 = fmaxf(p0, __shfl_xor_sync(~0u, p0, 2));
        p1 = fmaxf(p1, __shfl_xor_sync(~0u, p1, 1));
        p1 = fmaxf(p1, __shfl_xor_sync(~0u, p1, 2));
        const float mn0 = fmaxf(m0, p0), mn1 = fmaxf(m1, p1);
        const float a0 = __expf(m0 - mn0), a1 = __expf(m1 - mn1);
        m0 = mn0; m1 = mn1;

        float sum0 = 0.f, sum1 = 0.f;
        #pragma unroll
        for (int nt = 0; nt < 16; nt++) {
            s[nt][0] = __expf(s[nt][0] - m0); sum0 += s[nt][0];
            s[nt][1] = __expf(s[nt][1] - m0); sum0 += s[nt][1];
            s[nt][2] = __expf(s[nt][2] - m1); sum1 += s[nt][2];
            s[nt][3] = __expf(s[nt][3] - m1); sum1 += s[nt][3];
        }
        sum0 += __shfl_xor_sync(~0u, sum0, 1);
        sum0 += __shfl_xor_sync(~0u, sum0, 2);
        sum1 += __shfl_xor_sync(~0u, sum1, 1);
        sum1 += __shfl_xor_sync(~0u, sum1, 2);
        l0 = l0 * a0 + sum0;
        l1 = l1 * a1 + sum1;
        #pragma unroll
        for (int dt = 0; dt < 8; dt++) {
            o[dt][0] *= a0; o[dt][1] *= a0;
            o[dt][2] *= a1; o[dt][3] *= a1;
        }

        #pragma unroll
        for (int jk = 0; jk < 8; jk++) {
            uint32_t ah[4], al[4];
            pack2(s[2*jk][0],   s[2*jk][1],   ah[0], al[0]);
            pack2(s[2*jk][2],   s[2*jk][3],   ah[1], al[1]);
            pack2(s[2*jk+1][0], s[2*jk+1][1], ah[2], al[2]);
            pack2(s[2*jk+1][2], s[2*jk+1][3], ah[3], al[3]);
            #pragma unroll
            for (int dtp = 0; dtp < 4; dtp++) {
                const int r = jk * 16 + la;
                const int c = 2 * dtp + ca;
                const uint32_t vd = stb + 32768 + r * 128 + ((c ^ (r & 7)) * 16);
                uint32_t vh4[4], vl4[4];
                ldsm4t(vh4, vd);
                ldsm4t(vl4, vd + 16384);
                uint32_t vb0h[2] = {vh4[0], vh4[1]}, vb1h[2] = {vh4[2], vh4[3]};
                uint32_t vb0l[2] = {vl4[0], vl4[1]}, vb1l[2] = {vl4[2], vl4[3]};
                mma16(o[2*dtp],   ah, vb0h);
                mma16(o[2*dtp],   ah, vb0l);
                mma16(o[2*dtp],   al, vb0h);
                mma16(o[2*dtp+1], ah, vb1h);
                mma16(o[2*dtp+1], ah, vb1l);
                mma16(o[2*dtp+1], al, vb1h);
            }
        }

        __syncthreads();
        if (j < 7) {
            if (j + 2 < 8) { load_kv(j & 1, j + 2); cp_commit(); cp_wait<1>(); }
            else           { cp_wait<0>(); }
            __syncthreads();
        }
    }

    const float i0 = 1.0f / l0, i1 = 1.0f / l1;
    #pragma unroll
    for (int dt = 0; dt < 8; dt++) {
        const int cg = dt * 8 + 2 * t;
        #pragma unroll
        for (int h2 = 0; h2 < 2; h2++) {
            const int rg = row0 + warp * 16 + q + h2 * 8;
            const float inv = h2 ? i1 : i0;
            float v0 = o[dt][h2 * 2 + 0] * inv;
            float v1 = o[dt][h2 * 2 + 1] * inv;
            bf16 h0, lo0, h1, lo1;
            spbf(v0, h0, lo0); spbf(v1, h1, lo1);
            const long off = obase + (long)rg * H + cg;
            *(__nv_bfloat162*)(Ch + off) = __halves2bfloat162(h0, h1);
            *(__nv_bfloat162*)(Cl + off) = __halves2bfloat162(lo0, lo1);
        }
    }
}

// ---------------------------------------------------------------------------
// Prep (single launch): split hs; transpose+split all weights; pack QKV bias.
// ---------------------------------------------------------------------------
__device__ __forceinline__ void tr_tile(const float* in, bf16* oh, bf16* ol,
                                        int ldi, int ldo, int bx, int by,
                                        float (*tsm)[33])
{
    const int r0 = by * 32, c0 = bx * 32;
    const int tx = threadIdx.x & 31, ty = threadIdx.x >> 5;
    #pragma unroll
    for (int i = 0; i < 32; i += 8)
        tsm[ty + i][tx] = in[(long)(r0 + ty + i) * ldi + c0 + tx];
    __syncthreads();
    #pragma unroll
    for (int i = 0; i < 32; i += 8) {
        float v = tsm[tx][ty + i];
        bf16 hb, lb; spbf(v, hb, lb);
        long o = (long)(c0 + ty + i) * ldo + r0 + tx;
        oh[o] = hb; ol[o] = lb;
    }
}

__global__ void __launch_bounds__(256)
prep(const float* __restrict__ hs,
     const float* __restrict__ q_w, const float* __restrict__ k_w,
     const float* __restrict__ v_w, const float* __restrict__ ao_w,
     const float* __restrict__ ff1_w, const float* __restrict__ ff2_w,
     const float* __restrict__ q_b, const float* __restrict__ k_b,
     const float* __restrict__ v_b)
{
    __shared__ float tsm[32][33];
    const int b = blockIdx.x;
    if (b < 3072) {
        const int i = b * 256 + threadIdx.x;
        float4 v = ((const float4*)hs)[i];
        bf16 h0, l0, h1, l1;
        spbf(v.x, h0, l0); spbf(v.y, h1, l1);
        *(__nv_bfloat162*)(g_xh + i * 4) = __halves2bfloat162(h0, h1);
        *(__nv_bfloat162*)(g_xl + i * 4) = __halves2bfloat162(l0, l1);
        spbf(v.z, h0, l0); spbf(v.w, h1, l1);
        *(__nv_bfloat162*)(g_xh + i * 4 + 2) = __halves2bfloat162(h0, h1);
        *(__nv_bfloat162*)(g_xl + i * 4 + 2) = __halves2bfloat162(l0, l1);
    } else if (b < 3648) {
        int tt = b - 3072; tr_tile(q_w, g_wqkvh, g_wqkvl, H, H, tt % 24, tt / 24, tsm);
    } else if (b < 4224) {
        int tt = b - 3648; tr_tile(k_w, g_wqkvh + H*H, g_wqkvl + H*H, H, H, tt % 24, tt / 24, tsm);
    } else if (b < 4800) {
        int tt = b - 4224; tr_tile(v_w, g_wqkvh + 2*H*H, g_wqkvl + 2*H*H, H, H, tt % 24, tt / 24, tsm);
    } else if (b < 5376) {
        int tt = b - 4800; tr_tile(ao_w, g_wah, g_wal, H, H, tt % 24, tt / 24, tsm);
    } else if (b < 7680) {
        int tt = b - 5376; tr_tile(ff1_w, g_w1h, g_w1l, FFD, H, tt % 96, tt / 96, tsm);
    } else if (b < 9984) {
        int tt = b - 7680; tr_tile(ff2_w, g_w2h, g_w2l, H, FFD, tt % 24, tt / 24, tsm);
    } else {
        const int i = (b - 9984) * 256 + threadIdx.x;
        float v = (i < H) ? q_b[i] : (i < 2*H) ? k_b[i - H] : v_b[i - 2*H];
        g_bqkv[i] = v;
    }
}

// ---------------------------------------------------------------------------
// LayerNorm row H=768; warp-shuffle reductions.
// ---------------------------------------------------------------------------
template<bool SPLIT>
__global__ void __launch_bounds__(256)
ln_rows(const float* __restrict__ in, const float* __restrict__ g,
        const float* __restrict__ b, float* __restrict__ out,
        bf16* __restrict__ oh, bf16* __restrict__ ol)
{
    const long off = (long)blockIdx.x * H;
    const float* p = in + off;
    const int tid = threadIdx.x, lane = tid & 31, warp = tid >> 5;
    __shared__ float rs[8], rq[8];
    const float x0 = p[tid], x1 = p[tid + 256], x2 = p[tid + 512];
    float s  = x0 + x1 + x2;
    float sq = x0 * x0 + x1 * x1 + x2 * x2;
    #pragma unroll
    for (int o = 16; o > 0; o >>= 1) {
        s  += __shfl_xor_sync(~0u, s,  o);
        sq += __shfl_xor_sync(~0u, sq, o);
    }
    if (lane == 0) { rs[warp] = s; rq[warp] = sq; }
    __syncthreads();
    float ts = 0.f, tq = 0.f;
    #pragma unroll
    for (int i = 0; i < 8; i++) { ts += rs[i]; tq += rq[i]; }
    const float mean = ts * (1.0f / H);
    const float var  = tq * (1.0f / H) - mean * mean;
    const float inv  = rsqrtf(var + 1e-5f);
    #pragma unroll
    for (int i = 0; i < 3; i++) {
        const int c = tid + i * 256;
        const float xv = (i == 0 ? x0 : (i == 1 ? x1 : x2));
        const float o = (xv - mean) * inv * g[c] + b[c];
        out[off + c] = o;
        if (SPLIT) {
            bf16 hb, lb; spbf(o, hb, lb);
            oh[off + c] = hb; ol[off + c] = lb;
        }
    }
}

// ---------------------------------------------------------------------------
extern "C" void kernel_launch(void* const* d_in, const int* in_sizes, int n_in,
                              void* d_out, int out_size)
{
    const float* hs    = (const float*)d_in[0];
    const float* mask  = (const float*)d_in[1];
    const float* q_w   = (const float*)d_in[2];
    const float* q_b   = (const float*)d_in[3];
    const float* k_w   = (const float*)d_in[4];
    const float* k_b   = (const float*)d_in[5];
    const float* v_w   = (const float*)d_in[6];
    const float* v_b   = (const float*)d_in[7];
    const float* ao_w  = (const float*)d_in[8];
    const float* ao_b  = (const float*)d_in[9];
    const float* ln1_g = (const float*)d_in[10];
    const float* ln1_b = (const float*)d_in[11];
    const float* ff1_w = (const float*)d_in[12];
    const float* ff1_b = (const float*)d_in[13];
    const float* ff2_w = (const float*)d_in[14];
    const float* ff2_b = (const float*)d_in[15];
    const float* ln2_g = (const float*)d_in[16];
    const float* ln2_b = (const float*)d_in[17];
    float* out = (float*)d_out;

    float *x, *t, *at, *bqkv;
    bf16 *xh,*xl,*qkvh,*qkvl,*ch,*cl,*ah,*al,*fh,*fl;
    bf16 *wqkvh,*wqkvl,*wah,*wal,*w1h,*w1l,*w2h,*w2l;
    cudaGetSymbolAddress((void**)&x, g_x);
    cudaGetSymbolAddress((void**)&t, g_t);      cudaGetSymbolAddress((void**)&at, g_at);
    cudaGetSymbolAddress((void**)&bqkv, g_bqkv);
    cudaGetSymbolAddress((void**)&xh, g_xh);    cudaGetSymbolAddress((void**)&xl, g_xl);
    cudaGetSymbolAddress((void**)&qkvh, g_qkvh);cudaGetSymbolAddress((void**)&qkvl, g_qkvl);
    cudaGetSymbolAddress((void**)&ch, g_ch);    cudaGetSymbolAddress((void**)&cl, g_cl);
    cudaGetSymbolAddress((void**)&ah, g_ah);    cudaGetSymbolAddress((void**)&al, g_al);
    cudaGetSymbolAddress((void**)&fh, g_fh);    cudaGetSymbolAddress((void**)&fl, g_fl);
    cudaGetSymbolAddress((void**)&wqkvh, g_wqkvh);
    cudaGetSymbolAddress((void**)&wqkvl, g_wqkvl);
    cudaGetSymbolAddress((void**)&wah, g_wah);  cudaGetSymbolAddress((void**)&wal, g_wal);
    cudaGetSymbolAddress((void**)&w1h, g_w1h);  cudaGetSymbolAddress((void**)&w1l, g_w1l);
    cudaGetSymbolAddress((void**)&w2h, g_w2h);  cudaGetSymbolAddress((void**)&w2l, g_w2l);

    const int SMB = 98304;    // 3 stages x 32768; x2 CTAs = 196608 B/SM
    cudaFuncSetAttribute(gemm_bf<EPI_BIAS,   OUT_SPLIT>, cudaFuncAttributeMaxDynamicSharedMemorySize, SMB);
    cudaFuncSetAttribute(gemm_bf<EPI_BIASRES,OUT_F32>,   cudaFuncAttributeMaxDynamicSharedMemorySize, SMB);
    cudaFuncSetAttribute(gemm_bf<EPI_GELU,   OUT_SPLIT>, cudaFuncAttributeMaxDynamicSharedMemorySize, SMB);
    const int SMF = 167936;   // 164 KB
    cudaFuncSetAttribute(fattn, cudaFuncAttributeMaxDynamicSharedMemorySize, SMF);

    cudaMemcpyAsync(x, hs, (size_t)NTOK * H * sizeof(float), cudaMemcpyDeviceToDevice);
    prep<<<9993, 256>>>(hs, q_w, k_w, v_w, ao_w, ff1_w, ff2_w, q_b, k_b, v_b);

    const dim3 gQKV(18, 32), gProj(6, 32), gFF1(24, 32), gAtt(8, 48);

    for (int layer = 0; layer < NLAYER; layer++) {
        gemm_bf<EPI_BIAS, OUT_SPLIT><<<gQKV, 256, SMB>>>(
            xh, xl, wqkvh, wqkvl, bqkv, nullptr, nullptr, qkvh, qkvl,
            H, H, H, H3);

        fattn<<<gAtt, 256, SMF>>>(qkvh, qkvl, mask, ch, cl);

        gemm_bf<EPI_BIASRES, OUT_F32><<<gProj, 256, SMB>>>(
            ch, cl, wah, wal, ao_b, x, t, nullptr, nullptr, H, H, H, H);
        ln_rows<true><<<NTOK, 256>>>(t, ln1_g, ln1_b, at, ah, al);

        gemm_bf<EPI_GELU, OUT_SPLIT><<<gFF1, 256, SMB>>>(
            ah, al, w1h, w1l, ff1_b, nullptr, nullptr, fh, fl, H, H, H, FFD);
        gemm_bf<EPI_BIASRES, OUT_F32><<<gProj, 256, SMB>>>(
            fh, fl, w2h, w2l, ff2_b, at, t, nullptr, nullptr, FFD, FFD, FFD, H);

        if (layer == NLAYER - 1) {
            ln_rows<false><<<NTOK, 256>>>(t, ln2_g, ln2_b, out, nullptr, nullptr);
        } else {
            ln_rows<true><<<NTOK, 256>>>(t, ln2_g, ln2_b, x, xh, xl);
        }
    }
}

// round 17
// speedup vs baseline: 1.0716x; 1.0716x over previous
#include <cuda_runtime.h>
#include <cuda_bf16.h>
#include <math.h>
#include <stdint.h>

#define H    768
#define FFD  3072
#define BB   4
#define SS   1024
#define NHH  12
#define HDD  64
#define NTOK 4096
#define NLAYER 6
#define H3   2304   // 3*H packed QKV

typedef __nv_bfloat16 bf16;

// ---------------- device scratch ----------------
__device__ float g_t [NTOK*H];
__device__ float g_at[NTOK*H];
__device__ float g_x [NTOK*H];
__device__ float g_bqkv[H3];
__device__ bf16 g_xh[NTOK*H],   g_xl[NTOK*H];
__device__ bf16 g_qkvh[NTOK*H3], g_qkvl[NTOK*H3];
__device__ bf16 g_ch[NTOK*H],   g_cl[NTOK*H];
__device__ bf16 g_ah[NTOK*H],   g_al[NTOK*H];
__device__ bf16 g_fh[NTOK*FFD], g_fl[NTOK*FFD];
__device__ bf16 g_wqkvh[H3*H],  g_wqkvl[H3*H];
__device__ bf16 g_wah[H*H],     g_wal[H*H];
__device__ bf16 g_w1h[H*FFD],   g_w1l[H*FFD];
__device__ bf16 g_w2h[H*FFD],   g_w2l[H*FFD];

#define EPI_NONE      0
#define EPI_BIAS      1
#define EPI_GELU      2
#define EPI_BIASRES   3
#define OUT_F32   0
#define OUT_SPLIT 1

__device__ __forceinline__ uint32_t su32(const void* p) {
    return (uint32_t)__cvta_generic_to_shared(p);
}
__device__ __forceinline__ void cpa16(void* s, const void* g) {
    asm volatile("cp.async.cg.shared.global [%0], [%1], 16;" :: "r"(su32(s)), "l"(g));
}
__device__ __forceinline__ void cp_commit() { asm volatile("cp.async.commit_group;"); }
template<int N> __device__ __forceinline__ void cp_wait() {
    asm volatile("cp.async.wait_group %0;" :: "n"(N));
}
__device__ __forceinline__ void mma16(float c[4], const uint32_t a[4], const uint32_t b[2]) {
    asm volatile(
        "mma.sync.aligned.m16n8k16.row.col.f32.bf16.bf16.f32 "
        "{%0,%1,%2,%3}, {%4,%5,%6,%7}, {%8,%9}, {%0,%1,%2,%3};\n"
        : "+f"(c[0]), "+f"(c[1]), "+f"(c[2]), "+f"(c[3])
        : "r"(a[0]), "r"(a[1]), "r"(a[2]), "r"(a[3]), "r"(b[0]), "r"(b[1]));
}
__device__ __forceinline__ void ldsm4(uint32_t r[4], uint32_t addr) {
    asm volatile("ldmatrix.sync.aligned.m8n8.x4.shared.b16 {%0,%1,%2,%3}, [%4];"
                 : "=r"(r[0]), "=r"(r[1]), "=r"(r[2]), "=r"(r[3]) : "r"(addr));
}
__device__ __forceinline__ void ldsm4t(uint32_t r[4], uint32_t addr) {
    asm volatile("ldmatrix.sync.aligned.m8n8.x4.trans.shared.b16 {%0,%1,%2,%3}, [%4];"
                 : "=r"(r[0]), "=r"(r[1]), "=r"(r[2]), "=r"(r[3]) : "r"(addr));
}
__device__ __forceinline__ void spbf(float x, bf16& hi, bf16& lo) {
    hi = __float2bfloat16(x);
    lo = __float2bfloat16(x - __bfloat162float(hi));
}
__device__ __forceinline__ void pack2(float x, float y, uint32_t& hi, uint32_t& lo) {
    bf16 hx = __float2bfloat16(x), hy = __float2bfloat16(y);
    bf16 lx = __float2bfloat16(x - __bfloat162float(hx));
    bf16 ly = __float2bfloat16(y - __bfloat162float(hy));
    hi = ((uint32_t)__bfloat16_as_ushort(hy) << 16) | __bfloat16_as_ushort(hx);
    lo = ((uint32_t)__bfloat16_as_ushort(ly) << 16) | __bfloat16_as_ushort(lx);
}

// ---------------------------------------------------------------------------
// bf16 split GEMM: C = (Ah+Al)(Bh+Bl)^T, 3 terms, fp32 accum.
// CTA tile 128x64, BK=32, 8 warps, ldmatrix fragments.
// 3-stage cp.async ring, one __syncthreads per chunk, 3 CTAs/SM.
// MMA issue is TERM-MAJOR: 8 independent accumulators between reuses.
// ---------------------------------------------------------------------------
template<int EPI, int OUTM>
__global__ void __launch_bounds__(256, 3)
gemm_bf(const bf16* __restrict__ Ah, const bf16* __restrict__ Al,
        const bf16* __restrict__ Bh, const bf16* __restrict__ Bl,
        const float* __restrict__ bias, const float* __restrict__ res,
        float* __restrict__ Cf, bf16* __restrict__ Ch, bf16* __restrict__ Cl,
        int K, int lda, int ldb, int ldc)
{
    extern __shared__ __align__(16) char smem[];   // 3 stages x 24576 B
    const int tid = threadIdx.x, lane = tid & 31, warp = tid >> 5;
    const int row0 = blockIdx.y * 128, col0 = blockIdx.x * 64;
    const int wm = warp & 3, wn = warp >> 2;
    const int q = lane >> 2, t = lane & 3;
    const int la = lane & 15, ca = lane >> 4;
    const int mb = lane >> 3;
    const int rb = ((mb >> 1) << 3) + (lane & 7), cb = mb & 1;
    const uint32_t sbase = su32(smem);

    auto load_stage = [&](int s, int k0) {
        char* base = smem + s * 24576;
        #pragma unroll
        for (int i = 0; i < 4; i++) {
            int c = tid + i * 256, tile = c >> 9, rem = c & 511;
            int r = rem >> 2, cj = rem & 3;
            const bf16* src = (tile ? Al : Ah) + (long)(row0 + r) * lda + k0 + cj * 8;
            cpa16(base + tile * 8192 + r * 64 + ((cj ^ ((r >> 1) & 3)) * 16), src);
        }
        #pragma unroll
        for (int i = 0; i < 2; i++) {
            int c = tid + i * 256, tile = c >> 8, rem = c & 255;
            int r = rem >> 2, cj = rem & 3;
            const bf16* src = (tile ? Bl : Bh) + (long)(col0 + r) * ldb + k0 + cj * 8;
            cpa16(base + 16384 + tile * 4096 + r * 64 + ((cj ^ ((r >> 1) & 3)) * 16), src);
        }
        cp_commit();
    };

    float acc[2][4][4] = {};

    auto compute = [&](int s) {
        const uint32_t ab = sbase + s * 24576;
        #pragma unroll
        for (int ks = 0; ks < 2; ks++) {
            uint32_t ahi[2][4], alo[2][4], bhi[4][2], blo[4][2];
            #pragma unroll
            for (int mt = 0; mt < 2; mt++) {
                const int r = wm * 32 + mt * 16 + la;
                const int c = 2 * ks + ca;
                const uint32_t ad = ab + r * 64 + ((c ^ ((r >> 1) & 3)) * 16);
                ldsm4(ahi[mt], ad);
                ldsm4(alo[mt], ad + 8192);
            }
            #pragma unroll
            for (int p = 0; p < 2; p++) {
                const int r = wn * 32 + p * 16 + rb;
                const int c = 2 * ks + cb;
                const uint32_t bd = ab + 16384 + r * 64 + ((c ^ ((r >> 1) & 3)) * 16);
                uint32_t th[4], tl[4];
                ldsm4(th, bd);
                ldsm4(tl, bd + 4096);
                bhi[2*p][0] = th[0]; bhi[2*p][1] = th[1];
                bhi[2*p+1][0] = th[2]; bhi[2*p+1][1] = th[3];
                blo[2*p][0] = tl[0]; blo[2*p][1] = tl[1];
                blo[2*p+1][0] = tl[2]; blo[2*p+1][1] = tl[3];
            }
            // term-major: each acc revisited only every 8 MMAs
            #pragma unroll
            for (int mt = 0; mt < 2; mt++)
                #pragma unroll
                for (int nt = 0; nt < 4; nt++) mma16(acc[mt][nt], ahi[mt], bhi[nt]);
            #pragma unroll
            for (int mt = 0; mt < 2; mt++)
                #pragma unroll
                for (int nt = 0; nt < 4; nt++) mma16(acc[mt][nt], ahi[mt], blo[nt]);
            #pragma unroll
            for (int mt = 0; mt < 2; mt++)
                #pragma unroll
                for (int nt = 0; nt < 4; nt++) mma16(acc[mt][nt], alo[mt], bhi[nt]);
        }
    };

    const int nIt = K >> 5;
    load_stage(0, 0);
    load_stage(1, 32);
    for (int it = 0; it < nIt; it++) {
        if (it + 1 < nIt) cp_wait<1>();
        else              cp_wait<0>();
        __syncthreads();   // stage it%3 ready; stage it-1 fully consumed
        if (it + 2 < nIt) load_stage((it + 2) % 3, (it + 2) << 5);
        compute(it % 3);
    }

    #pragma unroll
    for (int mt = 0; mt < 2; mt++)
        #pragma unroll
        for (int nt = 0; nt < 4; nt++) {
            const int cg = col0 + wn * 32 + nt * 8 + 2 * t;
            #pragma unroll
            for (int h2 = 0; h2 < 2; h2++) {
                const int rg = row0 + wm * 32 + mt * 16 + q + h2 * 8;
                float v0 = acc[mt][nt][h2 * 2 + 0];
                float v1 = acc[mt][nt][h2 * 2 + 1];
                if (EPI != EPI_NONE) {
                    v0 += bias[cg];
                    v1 += bias[cg + 1];
                    if (EPI == EPI_GELU) {
                        v0 = 0.5f * v0 * (1.0f + erff(v0 * 0.70710678118654752440f));
                        v1 = 0.5f * v1 * (1.0f + erff(v1 * 0.70710678118654752440f));
                    } else if (EPI == EPI_BIASRES) {
                        v0 += res[(long)rg * ldc + cg];
                        v1 += res[(long)rg * ldc + cg + 1];
                    }
                }
                const long o = (long)rg * ldc + cg;
                if (OUTM == OUT_F32) {
                    *(float2*)(Cf + o) = make_float2(v0, v1);
                } else {
                    bf16 h0, l0, h1, l1;
                    spbf(v0, h0, l0); spbf(v1, h1, l1);
                    *(__nv_bfloat162*)(Ch + o) = __halves2bfloat162(h0, h1);
                    *(__nv_bfloat162*)(Cl + o) = __halves2bfloat162(l0, l1);
                }
            }
        }
}

// ---------------------------------------------------------------------------
// Fused flash attention (unchanged, known-good).
// ---------------------------------------------------------------------------
__global__ void __launch_bounds__(256, 1)
fattn(const bf16* __restrict__ QKVh, const bf16* __restrict__ QKVl,
      const float* __restrict__ mask,
      bf16* __restrict__ Ch, bf16* __restrict__ Cl)
{
    extern __shared__ __align__(16) char smem[];
    const int tid = threadIdx.x, lane = tid & 31, warp = tid >> 5;
    const int bh = blockIdx.y, bb = bh / NHH, hh = bh % NHH;
    const int row0 = blockIdx.x * 128;
    const long ibase = (long)bb * SS * H3 + hh * HDD;
    const long obase = (long)bb * SS * H  + hh * HDD;
    const int q = lane >> 2, t = lane & 3;
    const int la = lane & 15, ca = lane >> 4;
    const int mb = lane >> 3;
    const int rb = ((mb >> 1) << 3) + (lane & 7), cb = mb & 1;
    const uint32_t sbase = su32(smem);
    float* mask_s = (float*)(smem + 163840);

    for (int i = tid; i < SS; i += 256) mask_s[i] = mask[(long)bb * SS + i];

    auto load_q = [&]() {
        #pragma unroll
        for (int i = 0; i < 8; i++) {
            int c = tid + i * 256, buf = c >> 10, rem = c & 1023;
            int r = rem >> 3, cj = rem & 7;
            const bf16* src = (buf ? QKVl : QKVh) + ibase + (long)(row0 + r) * H3 + cj * 8;
            cpa16(smem + buf * 16384 + r * 128 + ((cj ^ (r & 7)) * 16), src);
        }
    };
    auto load_kv = [&](int s, int blk) {
        char* sb = smem + 32768 + s * 65536;
        #pragma unroll
        for (int i = 0; i < 16; i++) {
            int c = tid + i * 256, buf = c >> 10, rem = c & 1023;
            int r = rem >> 3, cj = rem & 7;
            const bf16* arr = (buf & 1) ? QKVl : QKVh;
            const int coff = (buf >> 1) ? 2 * H : H;
            const bf16* src = arr + ibase + coff + (long)(blk * 128 + r) * H3 + cj * 8;
            cpa16(sb + buf * 16384 + r * 128 + ((cj ^ (r & 7)) * 16), src);
        }
    };

    load_q();
    load_kv(0, 0);
    cp_commit();
    load_kv(1, 1);
    cp_commit();
    cp_wait<1>();
    __syncthreads();

    uint32_t qfh[4][4], qfl[4][4];
    #pragma unroll
    for (int kk = 0; kk < 4; kk++) {
        const int r = warp * 16 + la;
        const int c = 2 * kk + ca;
        const uint32_t ad = sbase + r * 128 + ((c ^ (r & 7)) * 16);
        ldsm4(qfh[kk], ad);
        ldsm4(qfl[kk], ad + 16384);
    }

    float m0 = -INFINITY, m1 = -INFINITY, l0 = 0.f, l1 = 0.f;
    float o[8][4] = {};

    for (int j = 0; j < 8; j++) {
        const uint32_t stb = sbase + 32768 + (j & 1) * 65536;

        float s[16][4];
        #pragma unroll
        for (int i = 0; i < 16; i++)
            #pragma unroll
            for (int c = 0; c < 4; c++) s[i][c] = 0.f;
        #pragma unroll
        for (int p = 0; p < 8; p++) {
            #pragma unroll
            for (int kk = 0; kk < 4; kk++) {
                const int r = p * 16 + rb;
                const int c = 2 * kk + cb;
                const uint32_t bd = stb + r * 128 + ((c ^ (r & 7)) * 16);
                uint32_t th[4], tl[4];
                ldsm4(th, bd);
                ldsm4(tl, bd + 16384);
                uint32_t b0h[2] = {th[0], th[1]}, b1h[2] = {th[2], th[3]};
                uint32_t b0l[2] = {tl[0], tl[1]}, b1l[2] = {tl[2], tl[3]};
                mma16(s[2*p],   qfh[kk], b0h);
                mma16(s[2*p],   qfh[kk], b0l);
                mma16(s[2*p],   qfl[kk], b0h);
                mma16(s[2*p+1], qfh[kk], b1h);
                mma16(s[2*p+1], qfh[kk], b1l);
                mma16(s[2*p+1], qfl[kk], b1h);
            }
        }

        #pragma unroll
        for (int nt = 0; nt < 16; nt++) {
            const int cc = j * 128 + nt * 8 + 2 * t;
            const float mk0 = mask_s[cc], mk1 = mask_s[cc + 1];
            s[nt][0] = s[nt][0] * 0.125f + mk0;
            s[nt][1] = s[nt][1] * 0.125f + mk1;
            s[nt][2] = s[nt][2] * 0.125f + mk0;
            s[nt][3] = s[nt][3] * 0.125f + mk1;
        }

        float p0 = -INFINITY, p1 = -INFINITY;
        #pragma unroll
        for (int nt = 0; nt < 16; nt++) {
            p0 = fmaxf(p0, fmaxf(s[nt][0], s[nt][1]));
            p1 = fmaxf(p1, fmaxf(s[nt][2], s[nt][3]));
        }
        p0 = fmaxf(p0, __shfl_xor_sync(~0u, p0, 1));
        p0 = fmaxf(p0, __shfl_xor_sync(~0u, p0, 2));
        p1 = fmaxf(p1, __shfl_xor_sync(~0u, p1, 1));
        p1 = fmaxf(p1, __shfl_xor_sync(~0u, p1, 2));
        const float mn0 = fmaxf(m0, p0), mn1 = fmaxf(m1, p1);
        const float a0 = __expf(m0 - mn0), a1 = __expf(m1 - mn1);
        m0 = mn0; m1 = mn1;

        float sum0 = 0.f, sum1 = 0.f;
        #pragma unroll
        for (int nt = 0; nt < 16; nt++) {
            s[nt][0] = __expf(s[nt][0] - m0); sum0 += s[nt][0];
            s[nt][1] = __expf(s[nt][1] - m0); sum0 += s[nt][1];
            s[nt][2] = __expf(s[nt][2] - m1); sum1 += s[nt][2];
            s[nt][3] = __expf(s[nt][3] - m1); sum1 += s[nt][3];
        }
        sum0 += __shfl_xor_sync(~0u, sum0, 1);
        sum0 += __shfl_xor_sync(~0u, sum0, 2);
        sum1 += __shfl_xor_sync(~0u, sum1, 1);
        sum1 += __shfl_xor_sync(~0u, sum1, 2);
        l0 = l0 * a0 + sum0;
        l1 = l1 * a1 + sum1;
        #pragma unroll
        for (int dt = 0; dt < 8; dt++) {
            o[dt][0] *= a0; o[dt][1] *= a0;
            o[dt][2] *= a1; o[dt][3] *= a1;
        }

        #pragma unroll
        for (int jk = 0; jk < 8; jk++) {
            uint32_t ah[4], al[4];
            pack2(s[2*jk][0],   s[2*jk][1],   ah[0], al[0]);
            pack2(s[2*jk][2],   s[2*jk][3],   ah[1], al[1]);
            pack2(s[2*jk+1][0], s[2*jk+1][1], ah[2], al[2]);
            pack2(s[2*jk+1][2], s[2*jk+1][3], ah[3], al[3]);
            #pragma unroll
            for (int dtp = 0; dtp < 4; dtp++) {
                const int r = jk * 16 + la;
                const int c = 2 * dtp + ca;
                const uint32_t vd = stb + 32768 + r * 128 + ((c ^ (r & 7)) * 16);
                uint32_t vh4[4], vl4[4];
                ldsm4t(vh4, vd);
                ldsm4t(vl4, vd + 16384);
                uint32_t vb0h[2] = {vh4[0], vh4[1]}, vb1h[2] = {vh4[2], vh4[3]};
                uint32_t vb0l[2] = {vl4[0], vl4[1]}, vb1l[2] = {vl4[2], vl4[3]};
                mma16(o[2*dtp],   ah, vb0h);
                mma16(o[2*dtp],   ah, vb0l);
                mma16(o[2*dtp],   al, vb0h);
                mma16(o[2*dtp+1], ah, vb1h);
                mma16(o[2*dtp+1], ah, vb1l);
                mma16(o[2*dtp+1], al, vb1h);
            }
        }

        __syncthreads();
        if (j < 7) {
            if (j + 2 < 8) { load_kv(j & 1, j + 2); cp_commit(); cp_wait<1>(); }
            else           { cp_wait<0>(); }
            __syncthreads();
        }
    }

    const float i0 = 1.0f / l0, i1 = 1.0f / l1;
    #pragma unroll
    for (int dt = 0; dt < 8; dt++) {
        const int cg = dt * 8 + 2 * t;
        #pragma unroll
        for (int h2 = 0; h2 < 2; h2++) {
            const int rg = row0 + warp * 16 + q + h2 * 8;
            const float inv = h2 ? i1 : i0;
            float v0 = o[dt][h2 * 2 + 0] * inv;
            float v1 = o[dt][h2 * 2 + 1] * inv;
            bf16 h0, lo0, h1, lo1;
            spbf(v0, h0, lo0); spbf(v1, h1, lo1);
            const long off = obase + (long)rg * H + cg;
            *(__nv_bfloat162*)(Ch + off) = __halves2bfloat162(h0, h1);
            *(__nv_bfloat162*)(Cl + off) = __halves2bfloat162(lo0, lo1);
        }
    }
}

// ---------------------------------------------------------------------------
// Prep (single launch): split hs; transpose+split all weights; pack QKV bias.
// ---------------------------------------------------------------------------
__device__ __forceinline__ void tr_tile(const float* in, bf16* oh, bf16* ol,
                                        int ldi, int ldo, int bx, int by,
                                        float (*tsm)[33])
{
    const int r0 = by * 32, c0 = bx * 32;
    const int tx = threadIdx.x & 31, ty = threadIdx.x >> 5;
    #pragma unroll
    for (int i = 0; i < 32; i += 8)
        tsm[ty + i][tx] = in[(long)(r0 + ty + i) * ldi + c0 + tx];
    __syncthreads();
    #pragma unroll
    for (int i = 0; i < 32; i += 8) {
        float v = tsm[tx][ty + i];
        bf16 hb, lb; spbf(v, hb, lb);
        long o = (long)(c0 + ty + i) * ldo + r0 + tx;
        oh[o] = hb; ol[o] = lb;
    }
}

__global__ void __launch_bounds__(256)
prep(const float* __restrict__ hs,
     const float* __restrict__ q_w, const float* __restrict__ k_w,
     const float* __restrict__ v_w, const float* __restrict__ ao_w,
     const float* __restrict__ ff1_w, const float* __restrict__ ff2_w,
     const float* __restrict__ q_b, const float* __restrict__ k_b,
     const float* __restrict__ v_b)
{
    __shared__ float tsm[32][33];
    const int b = blockIdx.x;
    if (b < 3072) {
        const int i = b * 256 + threadIdx.x;
        float4 v = ((const float4*)hs)[i];
        bf16 h0, l0, h1, l1;
        spbf(v.x, h0, l0); spbf(v.y, h1, l1);
        *(__nv_bfloat162*)(g_xh + i * 4) = __halves2bfloat162(h0, h1);
        *(__nv_bfloat162*)(g_xl + i * 4) = __halves2bfloat162(l0, l1);
        spbf(v.z, h0, l0); spbf(v.w, h1, l1);
        *(__nv_bfloat162*)(g_xh + i * 4 + 2) = __halves2bfloat162(h0, h1);
        *(__nv_bfloat162*)(g_xl + i * 4 + 2) = __halves2bfloat162(l0, l1);
    } else if (b < 3648) {
        int tt = b - 3072; tr_tile(q_w, g_wqkvh, g_wqkvl, H, H, tt % 24, tt / 24, tsm);
    } else if (b < 4224) {
        int tt = b - 3648; tr_tile(k_w, g_wqkvh + H*H, g_wqkvl + H*H, H, H, tt % 24, tt / 24, tsm);
    } else if (b < 4800) {
        int tt = b - 4224; tr_tile(v_w, g_wqkvh + 2*H*H, g_wqkvl + 2*H*H, H, H, tt % 24, tt / 24, tsm);
    } else if (b < 5376) {
        int tt = b - 4800; tr_tile(ao_w, g_wah, g_wal, H, H, tt % 24, tt / 24, tsm);
    } else if (b < 7680) {
        int tt = b - 5376; tr_tile(ff1_w, g_w1h, g_w1l, FFD, H, tt % 96, tt / 96, tsm);
    } else if (b < 9984) {
        int tt = b - 7680; tr_tile(ff2_w, g_w2h, g_w2l, H, FFD, tt % 24, tt / 24, tsm);
    } else {
        const int i = (b - 9984) * 256 + threadIdx.x;
        float v = (i < H) ? q_b[i] : (i < 2*H) ? k_b[i - H] : v_b[i - 2*H];
        g_bqkv[i] = v;
    }
}

// ---------------------------------------------------------------------------
// LayerNorm row H=768; warp-shuffle reductions.
// ---------------------------------------------------------------------------
template<bool SPLIT>
__global__ void __launch_bounds__(256)
ln_rows(const float* __restrict__ in, const float* __restrict__ g,
        const float* __restrict__ b, float* __restrict__ out,
        bf16* __restrict__ oh, bf16* __restrict__ ol)
{
    const long off = (long)blockIdx.x * H;
    const float* p = in + off;
    const int tid = threadIdx.x, lane = tid & 31, warp = tid >> 5;
    __shared__ float rs[8], rq[8];
    const float x0 = p[tid], x1 = p[tid + 256], x2 = p[tid + 512];
    float s  = x0 + x1 + x2;
    float sq = x0 * x0 + x1 * x1 + x2 * x2;
    #pragma unroll
    for (int o = 16; o > 0; o >>= 1) {
        s  += __shfl_xor_sync(~0u, s,  o);
        sq += __shfl_xor_sync(~0u, sq, o);
    }
    if (lane == 0) { rs[warp] = s; rq[warp] = sq; }
    __syncthreads();
    float ts = 0.f, tq = 0.f;
    #pragma unroll
    for (int i = 0; i < 8; i++) { ts += rs[i]; tq += rq[i]; }
    const float mean = ts * (1.0f / H);
    const float var  = tq * (1.0f / H) - mean * mean;
    const float inv  = rsqrtf(var + 1e-5f);
    #pragma unroll
    for (int i = 0; i < 3; i++) {
        const int c = tid + i * 256;
        const float xv = (i == 0 ? x0 : (i == 1 ? x1 : x2));
        const float o = (xv - mean) * inv * g[c] + b[c];
        out[off + c] = o;
        if (SPLIT) {
            bf16 hb, lb; spbf(o, hb, lb);
            oh[off + c] = hb; ol[off + c] = lb;
        }
    }
}

// ---------------------------------------------------------------------------
extern "C" void kernel_launch(void* const* d_in, const int* in_sizes, int n_in,
                              void* d_out, int out_size)
{
    const float* hs    = (const float*)d_in[0];
    const float* mask  = (const float*)d_in[1];
    const float* q_w   = (const float*)d_in[2];
    const float* q_b   = (const float*)d_in[3];
    const float* k_w   = (const float*)d_in[4];
    const float* k_b   = (const float*)d_in[5];
    const float* v_w   = (const float*)d_in[6];
    const float* v_b   = (const float*)d_in[7];
    const float* ao_w  = (const float*)d_in[8];
    const float* ao_b  = (const float*)d_in[9];
    const float* ln1_g = (const float*)d_in[10];
    const float* ln1_b = (const float*)d_in[11];
    const float* ff1_w = (const float*)d_in[12];
    const float* ff1_b = (const float*)d_in[13];
    const float* ff2_w = (const float*)d_in[14];
    const float* ff2_b = (const float*)d_in[15];
    const float* ln2_g = (const float*)d_in[16];
    const float* ln2_b = (const float*)d_in[17];
    float* out = (float*)d_out;

    float *x, *t, *at, *bqkv;
    bf16 *xh,*xl,*qkvh,*qkvl,*ch,*cl,*ah,*al,*fh,*fl;
    bf16 *wqkvh,*wqkvl,*wah,*wal,*w1h,*w1l,*w2h,*w2l;
    cudaGetSymbolAddress((void**)&x, g_x);
    cudaGetSymbolAddress((void**)&t, g_t);      cudaGetSymbolAddress((void**)&at, g_at);
    cudaGetSymbolAddress((void**)&bqkv, g_bqkv);
    cudaGetSymbolAddress((void**)&xh, g_xh);    cudaGetSymbolAddress((void**)&xl, g_xl);
    cudaGetSymbolAddress((void**)&qkvh, g_qkvh);cudaGetSymbolAddress((void**)&qkvl, g_qkvl);
    cudaGetSymbolAddress((void**)&ch, g_ch);    cudaGetSymbolAddress((void**)&cl, g_cl);
    cudaGetSymbolAddress((void**)&ah, g_ah);    cudaGetSymbolAddress((void**)&al, g_al);
    cudaGetSymbolAddress((void**)&fh, g_fh);    cudaGetSymbolAddress((void**)&fl, g_fl);
    cudaGetSymbolAddress((void**)&wqkvh, g_wqkvh);
    cudaGetSymbolAddress((void**)&wqkvl, g_wqkvl);
    cudaGetSymbolAddress((void**)&wah, g_wah);  cudaGetSymbolAddress((void**)&wal, g_wal);
    cudaGetSymbolAddress((void**)&w1h, g_w1h);  cudaGetSymbolAddress((void**)&w1l, g_w1l);
    cudaGetSymbolAddress((void**)&w2h, g_w2h);  cudaGetSymbolAddress((void**)&w2l, g_w2l);

    const int SMB = 73728;    // 3 stages x 24576; x3 CTAs = 221184 B/SM
    cudaFuncSetAttribute(gemm_bf<EPI_BIAS,   OUT_SPLIT>, cudaFuncAttributeMaxDynamicSharedMemorySize, SMB);
    cudaFuncSetAttribute(gemm_bf<EPI_BIASRES,OUT_F32>,   cudaFuncAttributeMaxDynamicSharedMemorySize, SMB);
    cudaFuncSetAttribute(gemm_bf<EPI_GELU,   OUT_SPLIT>, cudaFuncAttributeMaxDynamicSharedMemorySize, SMB);
    const int SMF = 167936;   // 164 KB
    cudaFuncSetAttribute(fattn, cudaFuncAttributeMaxDynamicSharedMemorySize, SMF);

    cudaMemcpyAsync(x, hs, (size_t)NTOK * H * sizeof(float), cudaMemcpyDeviceToDevice);
    prep<<<9993, 256>>>(hs, q_w, k_w, v_w, ao_w, ff1_w, ff2_w, q_b, k_b, v_b);

    const dim3 gQKV(36, 32), gProj(12, 32), gFF1(48, 32), gAtt(8, 48);

    for (int layer = 0; layer < NLAYER; layer++) {
        gemm_bf<EPI_BIAS, OUT_SPLIT><<<gQKV, 256, SMB>>>(
            xh, xl, wqkvh, wqkvl, bqkv, nullptr, nullptr, qkvh, qkvl,
            H, H, H, H3);

        fattn<<<gAtt, 256, SMF>>>(qkvh, qkvl, mask, ch, cl);

        gemm_bf<EPI_BIASRES, OUT_F32><<<gProj, 256, SMB>>>(
            ch, cl, wah, wal, ao_b, x, t, nullptr, nullptr, H, H, H, H);
        ln_rows<true><<<NTOK, 256>>>(t, ln1_g, ln1_b, at, ah, al);

        gemm_bf<EPI_GELU, OUT_SPLIT><<<gFF1, 256, SMB>>>(
            ah, al, w1h, w1l, ff1_b, nullptr, nullptr, fh, fl, H, H, H, FFD);
        gemm_bf<EPI_BIASRES, OUT_F32><<<gProj, 256, SMB>>>(
            fh, fl, w2h, w2l, ff2_b, at, t, nullptr, nullptr, FFD, FFD, FFD, H);

        if (layer == NLAYER - 1) {
            ln_rows<false><<<NTOK, 256>>>(t, ln2_g, ln2_b, out, nullptr, nullptr);
        } else {
            ln_rows<true><<<NTOK, 256>>>(t, ln2_g, ln2_b, x, xh, xl);
        }
    }
}